// round 16
// baseline (speedup 1.0000x reference)
#include <cuda_runtime.h>
#include <cuda_bf16.h>

#define G 64
#define S (G*G*G)
#define L 64
#define NPTS 150000
#define PADW 72                      // padded channel stride (144B): ldmatrix conflict-free

// ---------------- scratch (device globals; no allocation allowed) ----------
__device__ float g_sums[S*L];                                  // 67 MB
__device__ float g_cnt[S];                                     // 1 MB
__device__ __align__(16) __nv_bfloat16 g_xh[S*L], g_xl[S*L];   // conv1 in hi/lo
__device__ __align__(16) __nv_bfloat16 g_yh[S*L], g_yl[S*L];   // conv1 out hi/lo
// conv weights in mma-fragment order:
// idx = ((((t*2+wn)*2+hl)*2+pr)*4+q)*32 + lane   (uint4 units)
__device__ __align__(16) uint4 g_wf1[27648], g_wf2[27648];
__device__ __align__(16) __nv_bfloat16 g_w2th[L*L], g_w2tl[L*L];      // W2^T [o][l]

__device__ __forceinline__ unsigned pack_bf2(__nv_bfloat16 a, __nv_bfloat16 b) {
    return ((unsigned)__bfloat16_as_ushort(b) << 16) | (unsigned)__bfloat16_as_ushort(a);
}
__device__ __forceinline__ void split_pack2(float a, float b, unsigned& h, unsigned& l) {
    __nv_bfloat16 ah = __float2bfloat16(a), bh = __float2bfloat16(b);
    __nv_bfloat16 al = __float2bfloat16(a - __bfloat162float(ah));
    __nv_bfloat16 bl = __float2bfloat16(b - __bfloat162float(bh));
    h = pack_bf2(ah, bh); l = pack_bf2(al, bl);
}
__device__ __forceinline__ void ldsm4(unsigned addr, unsigned& r0, unsigned& r1,
                                      unsigned& r2, unsigned& r3) {
    asm volatile("ldmatrix.sync.aligned.m8n8.x4.shared.b16 {%0,%1,%2,%3}, [%4];"
        : "=r"(r0), "=r"(r1), "=r"(r2), "=r"(r3) : "r"(addr));
}
__device__ __forceinline__ void mma16816(float* c, const unsigned* a,
                                         unsigned b0, unsigned b1) {
    asm volatile("mma.sync.aligned.m16n8k16.row.col.f32.bf16.bf16.f32 "
        "{%0,%1,%2,%3}, {%4,%5,%6,%7}, {%8,%9}, {%0,%1,%2,%3};"
        : "+f"(c[0]), "+f"(c[1]), "+f"(c[2]), "+f"(c[3])
        : "r"(a[0]), "r"(a[1]), "r"(a[2]), "r"(a[3]), "r"(b0), "r"(b1));
}
__device__ __forceinline__ void cp16(unsigned dst, const void* src) {
    asm volatile("cp.async.cg.shared.global [%0], [%1], 16;" :: "r"(dst), "l"(src));
}
#define CP_COMMIT() asm volatile("cp.async.commit_group;" ::: "memory")
#define CP_WAIT(n)  asm volatile("cp.async.wait_group %0;" :: "n"(n) : "memory")

// ---------------- repack: conv weights -> mma fragment order; W2^T ----------
__global__ void repack_all(const float* __restrict__ Cw1,
                           const float* __restrict__ Cw2,
                           const float* __restrict__ W2) {
    int b = blockIdx.x;
    if (b < 216) {
        int idx = b*256 + threadIdx.x;          // 0..55295
        if (idx >= 55296) return;
        int conv = idx >= 27648;
        int r = conv ? idx - 27648 : idx;
        int lane = r & 31;
        int q  = (r >> 5) & 3;
        int pr = (r >> 7) & 1;
        int hl = (r >> 8) & 1;
        int wn = (r >> 9) & 1;
        int t  = r >> 10;                        // 0..26
        const float* src = conv ? Cw2 : Cw1;
        unsigned comp[4];
        #pragma unroll
        for (int j = 0; j < 4; ++j) {
            int o  = wn*32 + pr*16 + (j >> 1)*8 + (lane >> 2);
            int i0 = q*16 + (j & 1)*8 + (lane & 3)*2;
            float v0 = src[(o*64 + i0)*27 + t];
            float v1 = src[(o*64 + i0 + 1)*27 + t];
            __nv_bfloat16 h0 = __float2bfloat16(v0), h1 = __float2bfloat16(v1);
            if (hl == 0) {
                comp[j] = pack_bf2(h0, h1);
            } else {
                __nv_bfloat16 l0 = __float2bfloat16(v0 - __bfloat162float(h0));
                __nv_bfloat16 l1 = __float2bfloat16(v1 - __bfloat162float(h1));
                comp[j] = pack_bf2(l0, l1);
            }
        }
        uint4 u = make_uint4(comp[0], comp[1], comp[2], comp[3]);
        if (conv) g_wf2[r] = u; else g_wf1[r] = u;
    } else {
        int idx = (b - 216)*256 + threadIdx.x;   // 0..4095
        if (idx >= 4096) return;
        int o = idx >> 6, l = idx & 63;
        float v = W2[l*64 + o];
        __nv_bfloat16 h = __float2bfloat16(v);
        g_w2th[idx] = h;
        g_w2tl[idx] = __float2bfloat16(v - __bfloat162float(h));
    }
}

// ---------------- normalize + bf16 hi/lo split -------------------------------
__global__ void normalize_split() {
    int idx = blockIdx.x * 256 + threadIdx.x;   // S*16 float4 groups
    float c = g_cnt[idx >> 4];
    float inv = c > 0.f ? 1.f / c : 0.f;
    float4 v = ((const float4*)g_sums)[idx];
    unsigned hp0, lp0, hp1, lp1;
    split_pack2(v.x*inv, v.y*inv, hp0, lp0);
    split_pack2(v.z*inv, v.w*inv, hp1, lp1);
    ((uint2*)g_xh)[idx] = make_uint2(hp0, hp1);
    ((uint2*)g_xl)[idx] = make_uint2(lp0, lp1);
}

// ---------------- tensor-core point MLP + atomic scatter --------------------
#define MA_BYTES (2*128*PADW*2)
#define MW_BYTES (2*64*PADW*2)
#define MC_OFF   (MA_BYTES + MW_BYTES)
#define MLP_SMEM (MC_OFF + 6656)

__global__ void __launch_bounds__(256) mlp_tc(
    const float* __restrict__ pos, const int* __restrict__ pts,
    const float* __restrict__ W1, const float* __restrict__ b1,
    const float* __restrict__ b2,
    const float* __restrict__ Wk1, const float* __restrict__ bk1,
    const float* __restrict__ Wk2, const float* __restrict__ bk2)
{
    extern __shared__ __align__(16) char sm[];
    __nv_bfloat16* smA = (__nv_bfloat16*)sm;               // [hl][128][PADW]
    __nv_bfloat16* smB = (__nv_bfloat16*)(sm + MA_BYTES);  // [hl][64 o][PADW]
    float* smC   = (float*)(sm + MC_OFF);
    float* pos_s = smC;
    float* W1s   = smC + 1152;
    float* b1s   = smC + 1344;
    float* b2s   = smC + 1408;
    float* Wk1s  = smC + 1472;
    float* bk1s  = smC + 1536;
    float* Wk2s  = smC + 1544;
    float* bk2s  = smC + 1552;
    int*   cell_s = (int*)(smC + 1556);
    float* feat_s = (float*)sm;

    const unsigned Abase = (unsigned)__cvta_generic_to_shared(smA);
    const unsigned Bbase = (unsigned)__cvta_generic_to_shared(smB);
    const int tid = threadIdx.x, wid = tid >> 5, lane = tid & 31;
    const int p0 = blockIdx.x * 48;

    {
        for (int idx = tid; idx < 1152; idx += 256)
            pos_s[idx] = pos[(size_t)p0*24 + idx];
        if (tid < 192) W1s[tid] = W1[tid];
        if (tid < 64)  { b1s[tid] = b1[tid]; b2s[tid] = b2[tid]; Wk1s[tid] = Wk1[tid]; }
        if (tid < 8)   { bk1s[tid] = bk1[tid]; Wk2s[tid] = Wk2[tid]; }
        if (tid == 0)  bk2s[0] = bk2[0];
        if (tid < 48) {
            int p = p0 + tid;
            cell_s[tid] = (pts[p*3]*G + pts[p*3+1])*G + pts[p*3+2];
        }
        for (int idx = tid; idx < 1024; idx += 256) {
            int row = idx >> 3, ch = idx & 7;
            int hl = row >> 6, o = row & 63;
            const __nv_bfloat16* s = (hl ? g_w2tl : g_w2th) + o*64 + ch*8;
            *(float4*)(smB + (hl*64 + o)*PADW + ch*8) = *(const float4*)s;
        }
    }
    __syncthreads();

    const int warp_m = wid & 3, warp_n = wid >> 2;
    const int t8 = lane >> 3, lr = lane & 7;
    unsigned aOff[2][2], bOff[2][2];
    #pragma unroll
    for (int hl = 0; hl < 2; ++hl) {
        #pragma unroll
        for (int mb = 0; mb < 2; ++mb) {
            int r = warp_m*32 + mb*16 + (t8 & 1)*8 + lr;
            aOff[hl][mb] = (unsigned)(((hl*128 + r)*PADW + (t8 >> 1)*8) * 2);
        }
        #pragma unroll
        for (int pr = 0; pr < 2; ++pr) {
            int n = warp_n*32 + pr*16 + (t8 >> 1)*8 + lr;
            bOff[hl][pr] = (unsigned)(((hl*64 + n)*PADW + (t8 & 1)*8) * 2);
        }
    }

    for (int batch = 0; batch < 3; ++batch) {
        {
            int r = tid >> 1, l0 = (tid & 1) * 32;
            int p = batch*16 + (r >> 3);
            int k = r & 7;
            float px = pos_s[p*24 + k*3 + 0];
            float py = pos_s[p*24 + k*3 + 1];
            float pz = pos_s[p*24 + k*3 + 2];
            unsigned* dH = (unsigned*)(smA + r*PADW + l0);
            unsigned* dL = (unsigned*)(smA + (128 + r)*PADW + l0);
            #pragma unroll
            for (int j = 0; j < 16; ++j) {
                int l = l0 + j*2;
                float v0 = px*W1s[l]   + py*W1s[64+l]   + pz*W1s[128+l]   + b1s[l];
                float v1 = px*W1s[l+1] + py*W1s[64+l+1] + pz*W1s[128+l+1] + b1s[l+1];
                v0 = v0 >= 0.f ? v0 : 0.01f*v0;
                v1 = v1 >= 0.f ? v1 : 0.01f*v1;
                unsigned hp, lp;
                split_pack2(v0, v1, hp, lp);
                dH[j] = hp; dL[j] = lp;
            }
        }
        __syncthreads();

        float acc[2][4][4];
        #pragma unroll
        for (int mb = 0; mb < 2; ++mb)
            #pragma unroll
            for (int nb = 0; nb < 4; ++nb)
                #pragma unroll
                for (int q = 0; q < 4; ++q) acc[mb][nb][q] = 0.f;

        #pragma unroll
        for (int k0 = 0; k0 < 64; k0 += 16) {
            unsigned ah[2][4], al[2][4], bh[2][4], bl[2][4];
            #pragma unroll
            for (int mb = 0; mb < 2; ++mb) {
                ldsm4(Abase + aOff[0][mb] + k0*2, ah[mb][0], ah[mb][1], ah[mb][2], ah[mb][3]);
                ldsm4(Abase + aOff[1][mb] + k0*2, al[mb][0], al[mb][1], al[mb][2], al[mb][3]);
            }
            #pragma unroll
            for (int pr = 0; pr < 2; ++pr) {
                ldsm4(Bbase + bOff[0][pr] + k0*2, bh[pr][0], bh[pr][1], bh[pr][2], bh[pr][3]);
                ldsm4(Bbase + bOff[1][pr] + k0*2, bl[pr][0], bl[pr][1], bl[pr][2], bl[pr][3]);
            }
            #pragma unroll
            for (int mb = 0; mb < 2; ++mb)
                #pragma unroll
                for (int nb = 0; nb < 4; ++nb) {
                    int pr = nb >> 1, sel = (nb & 1) << 1;
                    mma16816(acc[mb][nb], ah[mb], bh[pr][sel], bh[pr][sel+1]);
                }
            #pragma unroll
            for (int mb = 0; mb < 2; ++mb)
                #pragma unroll
                for (int nb = 0; nb < 4; ++nb) {
                    int pr = nb >> 1, sel = (nb & 1) << 1;
                    mma16816(acc[mb][nb], ah[mb], bl[pr][sel], bl[pr][sel+1]);
                }
            #pragma unroll
            for (int mb = 0; mb < 2; ++mb)
                #pragma unroll
                for (int nb = 0; nb < 4; ++nb) {
                    int pr = nb >> 1, sel = (nb & 1) << 1;
                    mma16816(acc[mb][nb], al[mb], bh[pr][sel], bh[pr][sel+1]);
                }
        }
        __syncthreads();

        {
            const int gid = lane >> 2, qid = lane & 3;
            #pragma unroll
            for (int mb = 0; mb < 2; ++mb)
                #pragma unroll
                for (int nb = 0; nb < 4; ++nb) {
                    int n = warp_n*32 + nb*8 + qid*2;
                    float2 bb = *(const float2*)&b2s[n];
                    #pragma unroll
                    for (int half = 0; half < 2; ++half) {
                        int m = warp_m*32 + mb*16 + gid + half*8;
                        *(float2*)&feat_s[m*66 + n] =
                            make_float2(acc[mb][nb][half*2+0] + bb.x,
                                        acc[mb][nb][half*2+1] + bb.y);
                    }
                }
        }
        __syncthreads();

        #pragma unroll
        for (int rep = 0; rep < 4; ++rep) {
            int idx = rep*256 + tid;
            int p = idx >> 6, l = idx & 63;
            float f[8];
            #pragma unroll
            for (int k = 0; k < 8; ++k) f[k] = feat_s[(p*8 + k)*66 + l];
            float f2 = bk2s[0];
            #pragma unroll
            for (int o = 0; o < 8; ++o) {
                float s = bk1s[o];
                #pragma unroll
                for (int k = 0; k < 8; ++k) s += Wk1s[o*8 + k] * f[k];
                s = s >= 0.f ? s : 0.01f*s;
                f2 += Wk2s[o] * s;
            }
            int cell = cell_s[batch*16 + p];
            atomicAdd(&g_sums[(size_t)cell*64 + l], f2);
            if (l == 0) atomicAdd(&g_cnt[cell], 1.0f);
        }
        __syncthreads();
    }
}

// ---------------- mma.sync conv3d — double-buffered 2-row A stages ----------
// Two 38 KB buffers (76 KB total, 3 CTAs/SM). Stage s = dzy 0..8; stage s+2
// issues right after compute(s) and lands during compute(s+1).
#define AB_ELEMS (2*2*66*PADW)                // 19008 elems per buffer
#define AB_BYTES (AB_ELEMS*2)                 // 38016 B
#define CONV_SMEM (2*AB_BYTES)                // 76032 B

template<bool SPLIT_OUT>
__global__ void __launch_bounds__(128, 3) conv_mma(
    const __nv_bfloat16* __restrict__ xh, const __nv_bfloat16* __restrict__ xl,
    const uint4* __restrict__ wfrag,
    const float* __restrict__ bias,
    float* __restrict__ outF,
    __nv_bfloat16* __restrict__ outH, __nv_bfloat16* __restrict__ outL)
{
    extern __shared__ __align__(16) char sm_raw[];
    __nv_bfloat16* smA = (__nv_bfloat16*)sm_raw;    // [buf][hl][hrow][66][PADW]
    const unsigned Abase = (unsigned)__cvta_generic_to_shared(smA);

    const int tid = threadIdx.x;
    const int wid = tid >> 5, lane = tid & 31;
    const int d0 = blockIdx.x >> 5;
    const int h0 = (blockIdx.x & 31) << 1;
    const int warp_m = wid & 1, warp_n = wid >> 1;

    const int t8 = lane >> 3, lr = lane & 7;
    unsigned aOff[2][4];
    #pragma unroll
    for (int hl = 0; hl < 2; ++hl)
        #pragma unroll
        for (int mb = 0; mb < 4; ++mb) {
            int r = warp_m*64 + mb*16 + (t8 & 1)*8 + lr;
            int hrow = r >> 6, w = r & 63;
            aOff[hl][mb] = (unsigned)((((hl*2 + hrow)*66 + w)*PADW + (t8 >> 1)*8) * 2);
        }

    const uint4* wp = wfrag + warp_n*512 + lane;

    float acc[4][4][4];
    #pragma unroll
    for (int mb = 0; mb < 4; ++mb)
        #pragma unroll
        for (int nb = 0; nb < 4; ++nb)
            #pragma unroll
            for (int q = 0; q < 4; ++q) acc[mb][nb][q] = 0.f;

    uint4 bcur[4], bnxt[4];
    #pragma unroll
    for (int i = 0; i < 4; ++i)
        bcur[i] = wp[(i >> 1)*256 + (i & 1)*128];   // t=0, q=0

    auto issueA = [&](int s, int b) {
        const int dz = s / 3, dy = s % 3;
        const int dd = d0 + dz - 1;
        const bool dValid = (unsigned)dd < (unsigned)G;
        const unsigned bufB = Abase + (unsigned)(b * AB_BYTES);
        __nv_bfloat16* bufP = smA + (size_t)b * AB_ELEMS;
        #pragma unroll
        for (int it = 0; it < 2; ++it) {
            const int task = tid + it*128;          // 0..255
            const int gA = task >> 6, hlA = gA >> 1, hrA = gA & 1, wA = task & 63;
            const int hin = h0 + dy - 1 + hrA;
            unsigned dstU = bufB + (unsigned)(((hlA*2 + hrA)*66 + wA + 1)*PADW)*2;
            if (dValid && (unsigned)hin < (unsigned)G) {
                const __nv_bfloat16* src = (hlA ? xl : xh) +
                    (((size_t)(dd*G + hin))*G + wA) * 64;
                #pragma unroll
                for (int j = 0; j < 8; ++j) cp16(dstU + j*16, src + j*8);
            } else {
                float4 z = make_float4(0.f, 0.f, 0.f, 0.f);
                float4* d4 = (float4*)(bufP + ((hlA*2 + hrA)*66 + wA + 1)*PADW);
                #pragma unroll
                for (int j = 0; j < 8; ++j) d4[j] = z;
            }
            if (wA == 0) {
                float4 z = make_float4(0.f, 0.f, 0.f, 0.f);
                float4* h4 = (float4*)(bufP + ((hlA*2 + hrA)*66)*PADW);
                #pragma unroll
                for (int j = 0; j < 8; ++j) h4[j] = z;
            }
            if (wA == 63) {
                float4 z = make_float4(0.f, 0.f, 0.f, 0.f);
                float4* h4 = (float4*)(bufP + ((hlA*2 + hrA)*66 + 65)*PADW);
                #pragma unroll
                for (int j = 0; j < 8; ++j) h4[j] = z;
            }
        }
        CP_COMMIT();
    };

    issueA(0, 0);
    issueA(1, 1);

    for (int s = 0; s < 9; ++s) {
        const int buf = s & 1;
        if (s < 8) { CP_WAIT(1); } else { CP_WAIT(0); }   // group s landed
        __syncthreads();                                  // visible CTA-wide

        const unsigned bufB = Abase + (unsigned)(buf * AB_BYTES);
        #pragma unroll
        for (int dx = 0; dx < 3; ++dx) {
            const int t = s*3 + dx;                       // taps in order 0..26
            const unsigned Adyx = bufB + (unsigned)(dx * PADW * 2);
            #pragma unroll
            for (int q = 0; q < 4; ++q) {
                int nt = t, nq = q + 1;
                if (nq == 4) { nq = 0; nt = (t == 26) ? 0 : t + 1; }
                const int noff = nt*1024 + nq*32;
                #pragma unroll
                for (int i = 0; i < 4; ++i)
                    bnxt[i] = wp[noff + (i >> 1)*256 + (i & 1)*128];

                #pragma unroll
                for (int mb = 0; mb < 4; ++mb) {
                    unsigned ah[4], al[4];
                    ldsm4(Adyx + aOff[0][mb] + q*32, ah[0], ah[1], ah[2], ah[3]);
                    ldsm4(Adyx + aOff[1][mb] + q*32, al[0], al[1], al[2], al[3]);
                    #pragma unroll
                    for (int nb = 0; nb < 4; ++nb) {
                        const unsigned* BH = (const unsigned*)&bcur[nb >> 1];
                        int sel = (nb & 1) << 1;
                        mma16816(acc[mb][nb], ah, BH[sel], BH[sel+1]);
                    }
                    #pragma unroll
                    for (int nb = 0; nb < 4; ++nb) {
                        const unsigned* BL = (const unsigned*)&bcur[2 + (nb >> 1)];
                        int sel = (nb & 1) << 1;
                        mma16816(acc[mb][nb], ah, BL[sel], BL[sel+1]);
                    }
                    #pragma unroll
                    for (int nb = 0; nb < 4; ++nb) {
                        const unsigned* BH = (const unsigned*)&bcur[nb >> 1];
                        int sel = (nb & 1) << 1;
                        mma16816(acc[mb][nb], al, BH[sel], BH[sel+1]);
                    }
                }
                #pragma unroll
                for (int i = 0; i < 4; ++i) bcur[i] = bnxt[i];
            }
        }

        __syncthreads();                 // all reads of buf done
        if (s + 2 <= 8) issueA(s + 2, buf);
    }

    const int gid = lane >> 2, qid = lane & 3;
    #pragma unroll
    for (int mb = 0; mb < 4; ++mb)
        #pragma unroll
        for (int nb = 0; nb < 4; ++nb) {
            int n = warp_n*32 + nb*8 + qid*2;
            float2 bb = *(const float2*)&bias[n];
            #pragma unroll
            for (int half = 0; half < 2; ++half) {
                int m = warp_m*64 + mb*16 + gid + half*8;
                int hrow = m >> 6, w = m & 63;
                size_t pos = ((size_t)((d0*G + h0 + hrow)*G + w))*64 + n;
                float v0 = fmaxf(acc[mb][nb][half*2+0] + bb.x, 0.f);
                float v1 = fmaxf(acc[mb][nb][half*2+1] + bb.y, 0.f);
                if (SPLIT_OUT) {
                    unsigned hp, lp;
                    split_pack2(v0, v1, hp, lp);
                    *(unsigned*)(outH + pos) = hp;
                    *(unsigned*)(outL + pos) = lp;
                } else {
                    *(float2*)(outF + pos) = make_float2(v0, v1);
                }
            }
        }
}

// ---------------- launch -----------------------------------------------------
extern "C" void kernel_launch(void* const* d_in, const int* in_sizes, int n_in,
                              void* d_out, int out_size)
{
    const float* pos = (const float*)d_in[0];
    const int*   pts = (const int*)d_in[1];
    const float* W1  = (const float*)d_in[2];
    const float* b1  = (const float*)d_in[3];
    const float* W2  = (const float*)d_in[4];
    const float* b2  = (const float*)d_in[5];
    const float* Wk1 = (const float*)d_in[6];
    const float* bk1 = (const float*)d_in[7];
    const float* Wk2 = (const float*)d_in[8];
    const float* bk2 = (const float*)d_in[9];
    const float* Cw1 = (const float*)d_in[10];
    const float* Cb1 = (const float*)d_in[11];
    const float* Cw2 = (const float*)d_in[12];
    const float* Cb2 = (const float*)d_in[13];
    float* out = (float*)d_out;

    void *pSums, *pCnt, *pXh, *pXl, *pYh, *pYl, *pWf1, *pWf2;
    cudaGetSymbolAddress(&pSums, g_sums);
    cudaGetSymbolAddress(&pCnt,  g_cnt);
    cudaGetSymbolAddress(&pXh,   g_xh);
    cudaGetSymbolAddress(&pXl,   g_xl);
    cudaGetSymbolAddress(&pYh,   g_yh);
    cudaGetSymbolAddress(&pYl,   g_yl);
    cudaGetSymbolAddress(&pWf1,  g_wf1);
    cudaGetSymbolAddress(&pWf2,  g_wf2);

    cudaFuncSetAttribute(mlp_tc, cudaFuncAttributeMaxDynamicSharedMemorySize, MLP_SMEM);
    cudaFuncSetAttribute(conv_mma<true>,  cudaFuncAttributeMaxDynamicSharedMemorySize, CONV_SMEM);
    cudaFuncSetAttribute(conv_mma<false>, cudaFuncAttributeMaxDynamicSharedMemorySize, CONV_SMEM);

    cudaMemsetAsync(pSums, 0, sizeof(float) * (size_t)S * L);
    cudaMemsetAsync(pCnt,  0, sizeof(float) * (size_t)S);

    repack_all<<<232, 256>>>(Cw1, Cw2, W2);
    mlp_tc<<<NPTS/48, 256, MLP_SMEM>>>(pos, pts, W1, b1, b2, Wk1, bk1, Wk2, bk2);
    normalize_split<<<16384, 256>>>();
    conv_mma<true><<<2048, 128, CONV_SMEM>>>(
        (const __nv_bfloat16*)pXh, (const __nv_bfloat16*)pXl,
        (const uint4*)pWf1, Cb1,
        nullptr, (__nv_bfloat16*)pYh, (__nv_bfloat16*)pYl);
    conv_mma<false><<<2048, 128, CONV_SMEM>>>(
        (const __nv_bfloat16*)pYh, (const __nv_bfloat16*)pYl,
        (const uint4*)pWf2, Cb2,
        out, nullptr, nullptr);
}

// round 17
// speedup vs baseline: 1.3413x; 1.3413x over previous
#include <cuda_runtime.h>
#include <cuda_bf16.h>
#include <cuda_fp16.h>

#define G 64
#define S (G*G*G)
#define L 64
#define NPTS 150000
#define PADW 72                      // padded channel stride (144B): ldmatrix conflict-free

// ---------------- scratch (device globals; no allocation allowed) ----------
__device__ float g_sums[S*L];                                  // 67 MB
__device__ float g_cnt[S];                                     // 1 MB
__device__ __align__(16) __half g_yh[S*L], g_yl[S*L];          // conv1 out fp16 hi/lo
// conv weights (fp16, single term) in mma-fragment order:
// idx = (((t*2+wn)*2+pr)*4+q)*32 + lane   (uint4 units)
__device__ __align__(16) uint4 g_wf1[13824], g_wf2[13824];
__device__ __align__(16) __nv_bfloat16 g_w2th[L*L], g_w2tl[L*L];      // W2^T [o][l]

__device__ __forceinline__ unsigned pack_bf2(__nv_bfloat16 a, __nv_bfloat16 b) {
    return ((unsigned)__bfloat16_as_ushort(b) << 16) | (unsigned)__bfloat16_as_ushort(a);
}
__device__ __forceinline__ void split_pack2(float a, float b, unsigned& h, unsigned& l) {
    __nv_bfloat16 ah = __float2bfloat16(a), bh = __float2bfloat16(b);
    __nv_bfloat16 al = __float2bfloat16(a - __bfloat162float(ah));
    __nv_bfloat16 bl = __float2bfloat16(b - __bfloat162float(bh));
    h = pack_bf2(ah, bh); l = pack_bf2(al, bl);
}
__device__ __forceinline__ unsigned pack_h2(__half a, __half b) {
    return ((unsigned)__half_as_ushort(b) << 16) | (unsigned)__half_as_ushort(a);
}
__device__ __forceinline__ void split_pack2h(float a, float b, unsigned& h, unsigned& l) {
    __half ah = __float2half_rn(a), bh = __float2half_rn(b);
    __half al = __float2half_rn(a - __half2float(ah));
    __half bl = __float2half_rn(b - __half2float(bh));
    h = pack_h2(ah, bh); l = pack_h2(al, bl);
}
__device__ __forceinline__ void ldsm4(unsigned addr, unsigned& r0, unsigned& r1,
                                      unsigned& r2, unsigned& r3) {
    asm volatile("ldmatrix.sync.aligned.m8n8.x4.shared.b16 {%0,%1,%2,%3}, [%4];"
        : "=r"(r0), "=r"(r1), "=r"(r2), "=r"(r3) : "r"(addr));
}
__device__ __forceinline__ void mma16816(float* c, const unsigned* a,
                                         unsigned b0, unsigned b1) {   // bf16 (MLP)
    asm volatile("mma.sync.aligned.m16n8k16.row.col.f32.bf16.bf16.f32 "
        "{%0,%1,%2,%3}, {%4,%5,%6,%7}, {%8,%9}, {%0,%1,%2,%3};"
        : "+f"(c[0]), "+f"(c[1]), "+f"(c[2]), "+f"(c[3])
        : "r"(a[0]), "r"(a[1]), "r"(a[2]), "r"(a[3]), "r"(b0), "r"(b1));
}
__device__ __forceinline__ void mma16816h(float* c, const unsigned* a,
                                          unsigned b0, unsigned b1) {  // fp16 (conv)
    asm volatile("mma.sync.aligned.m16n8k16.row.col.f32.f16.f16.f32 "
        "{%0,%1,%2,%3}, {%4,%5,%6,%7}, {%8,%9}, {%0,%1,%2,%3};"
        : "+f"(c[0]), "+f"(c[1]), "+f"(c[2]), "+f"(c[3])
        : "r"(a[0]), "r"(a[1]), "r"(a[2]), "r"(a[3]), "r"(b0), "r"(b1));
}
__device__ __forceinline__ void cp16(unsigned dst, const void* src) {
    asm volatile("cp.async.cg.shared.global [%0], [%1], 16;" :: "r"(dst), "l"(src));
}
#define CP_COMMIT() asm volatile("cp.async.commit_group;" ::: "memory")
#define CP_WAIT(n)  asm volatile("cp.async.wait_group %0;" :: "n"(n) : "memory")

// ---------------- repack: conv weights (fp16) -> fragment order; W2^T -------
__global__ void repack_all(const float* __restrict__ Cw1,
                           const float* __restrict__ Cw2,
                           const float* __restrict__ W2) {
    int b = blockIdx.x;
    if (b < 108) {
        int idx = b*256 + threadIdx.x;          // 0..27647
        if (idx >= 27648) return;
        int conv = idx >= 13824;
        int r = conv ? idx - 13824 : idx;
        int lane = r & 31;
        int q  = (r >> 5) & 3;
        int pr = (r >> 7) & 1;
        int wn = (r >> 8) & 1;
        int t  = r >> 9;                         // 0..26
        const float* src = conv ? Cw2 : Cw1;
        unsigned comp[4];
        #pragma unroll
        for (int j = 0; j < 4; ++j) {
            int o  = wn*32 + pr*16 + (j >> 1)*8 + (lane >> 2);
            int i0 = q*16 + (j & 1)*8 + (lane & 3)*2;
            float v0 = src[(o*64 + i0)*27 + t];
            float v1 = src[(o*64 + i0 + 1)*27 + t];
            comp[j] = pack_h2(__float2half_rn(v0), __float2half_rn(v1));
        }
        uint4 u = make_uint4(comp[0], comp[1], comp[2], comp[3]);
        if (conv) g_wf2[r] = u; else g_wf1[r] = u;
    } else {
        int idx = (b - 108)*256 + threadIdx.x;   // 0..4095
        if (idx >= 4096) return;
        int o = idx >> 6, l = idx & 63;
        float v = W2[l*64 + o];
        __nv_bfloat16 h = __float2bfloat16(v);
        g_w2th[idx] = h;
        g_w2tl[idx] = __float2bfloat16(v - __bfloat162float(h));
    }
}

// ---------------- tensor-core point MLP + atomic scatter (R12, proven) ------
#define MA_BYTES (2*128*PADW*2)
#define MW_BYTES (2*64*PADW*2)
#define MC_OFF   (MA_BYTES + MW_BYTES)
#define MLP_SMEM (MC_OFF + 6656)

__global__ void __launch_bounds__(256) mlp_tc(
    const float* __restrict__ pos, const int* __restrict__ pts,
    const float* __restrict__ W1, const float* __restrict__ b1,
    const float* __restrict__ b2,
    const float* __restrict__ Wk1, const float* __restrict__ bk1,
    const float* __restrict__ Wk2, const float* __restrict__ bk2)
{
    extern __shared__ __align__(16) char sm[];
    __nv_bfloat16* smA = (__nv_bfloat16*)sm;               // [hl][128][PADW]
    __nv_bfloat16* smB = (__nv_bfloat16*)(sm + MA_BYTES);  // [hl][64 o][PADW]
    float* smC   = (float*)(sm + MC_OFF);
    float* pos_s = smC;
    float* W1s   = smC + 1152;
    float* b1s   = smC + 1344;
    float* b2s   = smC + 1408;
    float* Wk1s  = smC + 1472;
    float* bk1s  = smC + 1536;
    float* Wk2s  = smC + 1544;
    float* bk2s  = smC + 1552;
    int*   cell_s = (int*)(smC + 1556);
    float* feat_s = (float*)sm;

    const unsigned Abase = (unsigned)__cvta_generic_to_shared(smA);
    const unsigned Bbase = (unsigned)__cvta_generic_to_shared(smB);
    const int tid = threadIdx.x, wid = tid >> 5, lane = tid & 31;
    const int p0 = blockIdx.x * 48;

    {
        for (int idx = tid; idx < 1152; idx += 256)
            pos_s[idx] = pos[(size_t)p0*24 + idx];
        if (tid < 192) W1s[tid] = W1[tid];
        if (tid < 64)  { b1s[tid] = b1[tid]; b2s[tid] = b2[tid]; Wk1s[tid] = Wk1[tid]; }
        if (tid < 8)   { bk1s[tid] = bk1[tid]; Wk2s[tid] = Wk2[tid]; }
        if (tid == 0)  bk2s[0] = bk2[0];
        if (tid < 48) {
            int p = p0 + tid;
            cell_s[tid] = (pts[p*3]*G + pts[p*3+1])*G + pts[p*3+2];
        }
        for (int idx = tid; idx < 1024; idx += 256) {
            int row = idx >> 3, ch = idx & 7;
            int hl = row >> 6, o = row & 63;
            const __nv_bfloat16* s = (hl ? g_w2tl : g_w2th) + o*64 + ch*8;
            *(float4*)(smB + (hl*64 + o)*PADW + ch*8) = *(const float4*)s;
        }
    }
    __syncthreads();

    const int warp_m = wid & 3, warp_n = wid >> 2;
    const int t8 = lane >> 3, lr = lane & 7;
    unsigned aOff[2][2], bOff[2][2];
    #pragma unroll
    for (int hl = 0; hl < 2; ++hl) {
        #pragma unroll
        for (int mb = 0; mb < 2; ++mb) {
            int r = warp_m*32 + mb*16 + (t8 & 1)*8 + lr;
            aOff[hl][mb] = (unsigned)(((hl*128 + r)*PADW + (t8 >> 1)*8) * 2);
        }
        #pragma unroll
        for (int pr = 0; pr < 2; ++pr) {
            int n = warp_n*32 + pr*16 + (t8 >> 1)*8 + lr;
            bOff[hl][pr] = (unsigned)(((hl*64 + n)*PADW + (t8 & 1)*8) * 2);
        }
    }

    for (int batch = 0; batch < 3; ++batch) {
        {
            int r = tid >> 1, l0 = (tid & 1) * 32;
            int p = batch*16 + (r >> 3);
            int k = r & 7;
            float px = pos_s[p*24 + k*3 + 0];
            float py = pos_s[p*24 + k*3 + 1];
            float pz = pos_s[p*24 + k*3 + 2];
            unsigned* dH = (unsigned*)(smA + r*PADW + l0);
            unsigned* dL = (unsigned*)(smA + (128 + r)*PADW + l0);
            #pragma unroll
            for (int j = 0; j < 16; ++j) {
                int l = l0 + j*2;
                float v0 = px*W1s[l]   + py*W1s[64+l]   + pz*W1s[128+l]   + b1s[l];
                float v1 = px*W1s[l+1] + py*W1s[64+l+1] + pz*W1s[128+l+1] + b1s[l+1];
                v0 = v0 >= 0.f ? v0 : 0.01f*v0;
                v1 = v1 >= 0.f ? v1 : 0.01f*v1;
                unsigned hp, lp;
                split_pack2(v0, v1, hp, lp);
                dH[j] = hp; dL[j] = lp;
            }
        }
        __syncthreads();

        float acc[2][4][4];
        #pragma unroll
        for (int mb = 0; mb < 2; ++mb)
            #pragma unroll
            for (int nb = 0; nb < 4; ++nb)
                #pragma unroll
                for (int q = 0; q < 4; ++q) acc[mb][nb][q] = 0.f;

        #pragma unroll
        for (int k0 = 0; k0 < 64; k0 += 16) {
            unsigned ah[2][4], al[2][4], bh[2][4], bl[2][4];
            #pragma unroll
            for (int mb = 0; mb < 2; ++mb) {
                ldsm4(Abase + aOff[0][mb] + k0*2, ah[mb][0], ah[mb][1], ah[mb][2], ah[mb][3]);
                ldsm4(Abase + aOff[1][mb] + k0*2, al[mb][0], al[mb][1], al[mb][2], al[mb][3]);
            }
            #pragma unroll
            for (int pr = 0; pr < 2; ++pr) {
                ldsm4(Bbase + bOff[0][pr] + k0*2, bh[pr][0], bh[pr][1], bh[pr][2], bh[pr][3]);
                ldsm4(Bbase + bOff[1][pr] + k0*2, bl[pr][0], bl[pr][1], bl[pr][2], bl[pr][3]);
            }
            #pragma unroll
            for (int mb = 0; mb < 2; ++mb)
                #pragma unroll
                for (int nb = 0; nb < 4; ++nb) {
                    int pr = nb >> 1, sel = (nb & 1) << 1;
                    mma16816(acc[mb][nb], ah[mb], bh[pr][sel], bh[pr][sel+1]);
                }
            #pragma unroll
            for (int mb = 0; mb < 2; ++mb)
                #pragma unroll
                for (int nb = 0; nb < 4; ++nb) {
                    int pr = nb >> 1, sel = (nb & 1) << 1;
                    mma16816(acc[mb][nb], ah[mb], bl[pr][sel], bl[pr][sel+1]);
                }
            #pragma unroll
            for (int mb = 0; mb < 2; ++mb)
                #pragma unroll
                for (int nb = 0; nb < 4; ++nb) {
                    int pr = nb >> 1, sel = (nb & 1) << 1;
                    mma16816(acc[mb][nb], al[mb], bh[pr][sel], bh[pr][sel+1]);
                }
        }
        __syncthreads();

        {
            const int gid = lane >> 2, qid = lane & 3;
            #pragma unroll
            for (int mb = 0; mb < 2; ++mb)
                #pragma unroll
                for (int nb = 0; nb < 4; ++nb) {
                    int n = warp_n*32 + nb*8 + qid*2;
                    float2 bb = *(const float2*)&b2s[n];
                    #pragma unroll
                    for (int half = 0; half < 2; ++half) {
                        int m = warp_m*32 + mb*16 + gid + half*8;
                        *(float2*)&feat_s[m*66 + n] =
                            make_float2(acc[mb][nb][half*2+0] + bb.x,
                                        acc[mb][nb][half*2+1] + bb.y);
                    }
                }
        }
        __syncthreads();

        #pragma unroll
        for (int rep = 0; rep < 4; ++rep) {
            int idx = rep*256 + tid;
            int p = idx >> 6, l = idx & 63;
            float f[8];
            #pragma unroll
            for (int k = 0; k < 8; ++k) f[k] = feat_s[(p*8 + k)*66 + l];
            float f2 = bk2s[0];
            #pragma unroll
            for (int o = 0; o < 8; ++o) {
                float s = bk1s[o];
                #pragma unroll
                for (int k = 0; k < 8; ++k) s += Wk1s[o*8 + k] * f[k];
                s = s >= 0.f ? s : 0.01f*s;
                f2 += Wk2s[o] * s;
            }
            int cell = cell_s[batch*16 + p];
            atomicAdd(&g_sums[(size_t)cell*64 + l], f2);
            if (l == 0) atomicAdd(&g_cnt[cell], 1.0f);
        }
        __syncthreads();
    }
}

// ---------------- fp16 2-term conv3d (R12 structure: 4-row A, 6 barriers) ---
#define A_ELEMS (2*4*66*PADW)                 // 38016 elems
#define A_BYTES (A_ELEMS*2)                   // 76032 B
#define CONV_SMEM A_BYTES                     // 3 CTAs/SM

template<bool SPLIT_OUT, bool READ_F32>
__global__ void __launch_bounds__(128, 3) conv_mma(
    const __half* __restrict__ xh, const __half* __restrict__ xl,
    const float* __restrict__ xf, const float* __restrict__ xcnt,
    const uint4* __restrict__ wfrag,
    const float* __restrict__ bias,
    float* __restrict__ outF,
    __half* __restrict__ outH, __half* __restrict__ outL)
{
    extern __shared__ __align__(16) char sm_raw[];
    __half* smA = (__half*)sm_raw;            // [hl][4 rows][66][PADW]
    const unsigned Abase = (unsigned)__cvta_generic_to_shared(smA);

    const int tid = threadIdx.x;
    const int wid = tid >> 5, lane = tid & 31;
    const int d0 = blockIdx.x >> 5;
    const int h0 = (blockIdx.x & 31) << 1;
    const int warp_m = wid & 1, warp_n = wid >> 1;

    const int t8 = lane >> 3, lr = lane & 7;
    unsigned aOff[2][4];
    #pragma unroll
    for (int hl = 0; hl < 2; ++hl)
        #pragma unroll
        for (int mb = 0; mb < 4; ++mb) {
            int r = warp_m*64 + mb*16 + (t8 & 1)*8 + lr;
            int hrow = r >> 6, w = r & 63;
            aOff[hl][mb] = (unsigned)((((hl*4 + hrow)*66 + w)*PADW + (t8 >> 1)*8) * 2);
        }

    // fragment ptr: + wn*256 + lane; offsets: t*512 + q*32, pr +128
    const uint4* wp = wfrag + warp_n*256 + lane;

    float acc[4][4][4];
    #pragma unroll
    for (int mb = 0; mb < 4; ++mb)
        #pragma unroll
        for (int nb = 0; nb < 4; ++nb)
            #pragma unroll
            for (int q = 0; q < 4; ++q) acc[mb][nb][q] = 0.f;

    uint4 bcur[2], bnxt[2];
    #pragma unroll
    for (int i = 0; i < 2; ++i)
        bcur[i] = wp[i*128];                   // t=0, q=0, pr=i

    for (int dz = 0; dz < 3; ++dz) {
        const int dd = d0 + dz - 1;
        const bool dValid = (unsigned)dd < (unsigned)G;

        __syncthreads();   // all reads of previous A done
        if (READ_F32) {
            for (int task = tid; task < 512; task += 128) {
                const int row = task >> 7;              // 0..3
                const int wA2 = (task >> 1) & 63;
                const int cH = task & 1;
                const int hin = h0 + row - 1;
                uint2* dH = (uint2*)(smA + ((0 + row)*66 + wA2 + 1)*PADW + cH*32);
                uint2* dL = (uint2*)(smA + ((4 + row)*66 + wA2 + 1)*PADW + cH*32);
                if (dValid && (unsigned)hin < (unsigned)G) {
                    size_t cell = (size_t)(dd*G + hin)*G + wA2;
                    float c = xcnt[cell];
                    float inv = c > 0.f ? 1.f/c : 0.f;
                    const float4* s4 = (const float4*)(xf + cell*64 + cH*32);
                    #pragma unroll
                    for (int j = 0; j < 8; ++j) {
                        float4 v = s4[j];
                        unsigned hp0, lp0, hp1, lp1;
                        split_pack2h(v.x*inv, v.y*inv, hp0, lp0);
                        split_pack2h(v.z*inv, v.w*inv, hp1, lp1);
                        dH[j] = make_uint2(hp0, hp1);
                        dL[j] = make_uint2(lp0, lp1);
                    }
                } else {
                    uint2 z = make_uint2(0u, 0u);
                    #pragma unroll
                    for (int j = 0; j < 8; ++j) { dH[j] = z; dL[j] = z; }
                }
                if (wA2 == 0) {
                    uint2 z = make_uint2(0u, 0u);
                    uint2* zh = (uint2*)(smA + ((0 + row)*66)*PADW + cH*32);
                    uint2* zl = (uint2*)(smA + ((4 + row)*66)*PADW + cH*32);
                    #pragma unroll
                    for (int j = 0; j < 8; ++j) { zh[j] = z; zl[j] = z; }
                }
                if (wA2 == 63) {
                    uint2 z = make_uint2(0u, 0u);
                    uint2* zh = (uint2*)(smA + ((0 + row)*66 + 65)*PADW + cH*32);
                    uint2* zl = (uint2*)(smA + ((4 + row)*66 + 65)*PADW + cH*32);
                    #pragma unroll
                    for (int j = 0; j < 8; ++j) { zh[j] = z; zl[j] = z; }
                }
            }
        } else {
            for (int task = tid; task < 512; task += 128) {
                const int gA = task >> 6, hlA = gA >> 2, row = gA & 3, wA = task & 63;
                const int hin = h0 + row - 1;
                unsigned dstU = Abase + (unsigned)(((hlA*4 + row)*66 + wA + 1)*PADW)*2;
                if (dValid && (unsigned)hin < (unsigned)G) {
                    const __half* src = (hlA ? xl : xh) +
                        (((size_t)(dd*G + hin))*G + wA) * 64;
                    #pragma unroll
                    for (int j = 0; j < 8; ++j) cp16(dstU + j*16, src + j*8);
                } else {
                    float4 z = make_float4(0.f, 0.f, 0.f, 0.f);
                    float4* d4 = (float4*)(smA + ((hlA*4 + row)*66 + wA + 1)*PADW);
                    #pragma unroll
                    for (int j = 0; j < 8; ++j) d4[j] = z;
                }
                if (wA == 0) {
                    float4 z = make_float4(0.f, 0.f, 0.f, 0.f);
                    float4* h4 = (float4*)(smA + ((hlA*4 + row)*66)*PADW);
                    #pragma unroll
                    for (int j = 0; j < 8; ++j) h4[j] = z;
                }
                if (wA == 63) {
                    float4 z = make_float4(0.f, 0.f, 0.f, 0.f);
                    float4* h4 = (float4*)(smA + ((hlA*4 + row)*66 + 65)*PADW);
                    #pragma unroll
                    for (int j = 0; j < 8; ++j) h4[j] = z;
                }
            }
            CP_COMMIT();
            CP_WAIT(0);
        }
        __syncthreads();   // A tile visible CTA-wide

        #pragma unroll
        for (int dy = 0; dy < 3; ++dy) {
            #pragma unroll
            for (int dx = 0; dx < 3; ++dx) {
                const int t = (dz*3 + dy)*3 + dx;
                const unsigned Adyx = Abase + (unsigned)((dy*66 + dx) * PADW * 2);
                #pragma unroll
                for (int q = 0; q < 4; ++q) {
                    int nt = t, nq = q + 1;
                    if (nq == 4) { nq = 0; nt = (t == 26) ? 0 : t + 1; }
                    const int noff = nt*512 + nq*32;
                    #pragma unroll
                    for (int i = 0; i < 2; ++i)
                        bnxt[i] = wp[noff + i*128];

                    #pragma unroll
                    for (int mb = 0; mb < 4; ++mb) {
                        unsigned ah[4], al[4];
                        ldsm4(Adyx + aOff[0][mb] + q*32, ah[0], ah[1], ah[2], ah[3]);
                        ldsm4(Adyx + aOff[1][mb] + q*32, al[0], al[1], al[2], al[3]);
                        #pragma unroll
                        for (int nb = 0; nb < 4; ++nb) {
                            const unsigned* BH = (const unsigned*)&bcur[nb >> 1];
                            int sel = (nb & 1) << 1;
                            mma16816h(acc[mb][nb], ah, BH[sel], BH[sel+1]);
                        }
                        #pragma unroll
                        for (int nb = 0; nb < 4; ++nb) {
                            const unsigned* BH = (const unsigned*)&bcur[nb >> 1];
                            int sel = (nb & 1) << 1;
                            mma16816h(acc[mb][nb], al, BH[sel], BH[sel+1]);
                        }
                    }
                    #pragma unroll
                    for (int i = 0; i < 2; ++i) bcur[i] = bnxt[i];
                }
            }
        }
    }

    const int gid = lane >> 2, qid = lane & 3;
    #pragma unroll
    for (int mb = 0; mb < 4; ++mb)
        #pragma unroll
        for (int nb = 0; nb < 4; ++nb) {
            int n = warp_n*32 + nb*8 + qid*2;
            float2 bb = *(const float2*)&bias[n];
            #pragma unroll
            for (int half = 0; half < 2; ++half) {
                int m = warp_m*64 + mb*16 + gid + half*8;
                int hrow = m >> 6, w = m & 63;
                size_t pos = ((size_t)((d0*G + h0 + hrow)*G + w))*64 + n;
                float v0 = fmaxf(acc[mb][nb][half*2+0] + bb.x, 0.f);
                float v1 = fmaxf(acc[mb][nb][half*2+1] + bb.y, 0.f);
                if (SPLIT_OUT) {
                    unsigned hp, lp;
                    split_pack2h(v0, v1, hp, lp);
                    *(unsigned*)(outH + pos) = hp;
                    *(unsigned*)(outL + pos) = lp;
                } else {
                    *(float2*)(outF + pos) = make_float2(v0, v1);
                }
            }
        }
}

// ---------------- launch -----------------------------------------------------
extern "C" void kernel_launch(void* const* d_in, const int* in_sizes, int n_in,
                              void* d_out, int out_size)
{
    const float* pos = (const float*)d_in[0];
    const int*   pts = (const int*)d_in[1];
    const float* W1  = (const float*)d_in[2];
    const float* b1  = (const float*)d_in[3];
    const float* W2  = (const float*)d_in[4];
    const float* b2  = (const float*)d_in[5];
    const float* Wk1 = (const float*)d_in[6];
    const float* bk1 = (const float*)d_in[7];
    const float* Wk2 = (const float*)d_in[8];
    const float* bk2 = (const float*)d_in[9];
    const float* Cw1 = (const float*)d_in[10];
    const float* Cb1 = (const float*)d_in[11];
    const float* Cw2 = (const float*)d_in[12];
    const float* Cb2 = (const float*)d_in[13];
    float* out = (float*)d_out;

    void *pSums, *pCnt, *pYh, *pYl, *pWf1, *pWf2;
    cudaGetSymbolAddress(&pSums, g_sums);
    cudaGetSymbolAddress(&pCnt,  g_cnt);
    cudaGetSymbolAddress(&pYh,   g_yh);
    cudaGetSymbolAddress(&pYl,   g_yl);
    cudaGetSymbolAddress(&pWf1,  g_wf1);
    cudaGetSymbolAddress(&pWf2,  g_wf2);

    cudaFuncSetAttribute(mlp_tc, cudaFuncAttributeMaxDynamicSharedMemorySize, MLP_SMEM);
    cudaFuncSetAttribute(conv_mma<true,true>,   cudaFuncAttributeMaxDynamicSharedMemorySize, CONV_SMEM);
    cudaFuncSetAttribute(conv_mma<false,false>, cudaFuncAttributeMaxDynamicSharedMemorySize, CONV_SMEM);

    cudaMemsetAsync(pSums, 0, sizeof(float) * (size_t)S * L);
    cudaMemsetAsync(pCnt,  0, sizeof(float) * (size_t)S);

    repack_all<<<124, 256>>>(Cw1, Cw2, W2);
    mlp_tc<<<NPTS/48, 256, MLP_SMEM>>>(pos, pts, W1, b1, b2, Wk1, bk1, Wk2, bk2);
    conv_mma<true,true><<<2048, 128, CONV_SMEM>>>(
        nullptr, nullptr, (const float*)pSums, (const float*)pCnt,
        (const uint4*)pWf1, Cb1,
        nullptr, (__half*)pYh, (__half*)pYl);
    conv_mma<false,false><<<2048, 128, CONV_SMEM>>>(
        (const __half*)pYh, (const __half*)pYl, nullptr, nullptr,
        (const uint4*)pWf2, Cb2,
        out, nullptr, nullptr);
}